// round 9
// baseline (speedup 1.0000x reference)
#include <cuda_runtime.h>
#include <cuda_fp16.h>
#include <math.h>
#include <stdint.h>

#define DMODEL 1024
#define DINNER 2048
#define DSTATE 16
#define SEQLEN 2048
#define NTOK   4096   /* BATCH * SEQLEN */

// ---------------- scratch (device globals; no runtime allocation) ----------------
__device__ __half g_xh [NTOK * DMODEL];
__device__ __half g_wzh[DINNER * DMODEL];
__device__ __half g_wth[DMODEL * DINNER];     // WxcT hi
__device__ __half g_Ph [4u * DINNER * DINNER];
__device__ __half g_Mbh[DINNER * 4 * DMODEL]; // folded conv weights, conv layout
__device__ __half g_dwh[DINNER * DINNER];
__device__ __half g_owh[DMODEL * DINNER];
__device__ __half g_uh [NTOK * DINNER];       // conv output (f16 only)
__device__ __half g_sh [NTOK * DINNER];       // silu(z) (f16 only)
__device__ float  g_dt [NTOK * DINNER];       // dt kept fp32 (exp-argument sensitivity)
__device__ __half g_yh [NTOK * DINNER];
__device__ float  g_Bm [NTOK * DSTATE], g_Cm [NTOK * DSTATE];

// ---------------- helpers ----------------
__device__ __forceinline__ uint32_t smem_u32(const void* p) {
    uint32_t a;
    asm("{ .reg .u64 t; cvta.to.shared.u64 t, %1; cvt.u32.u64 %0, t; }" : "=r"(a) : "l"(p));
    return a;
}

#define LDSM4(r, a) asm volatile( \
    "ldmatrix.sync.aligned.m8n8.x4.shared.b16 {%0,%1,%2,%3}, [%4];" \
    : "=r"((r)[0]), "=r"((r)[1]), "=r"((r)[2]), "=r"((r)[3]) : "r"(a))

#define MMAF32(c, a, b0, b1) asm volatile( \
    "mma.sync.aligned.m16n8k16.row.col.f32.f16.f16.f32 " \
    "{%0,%1,%2,%3},{%4,%5,%6,%7},{%8,%9},{%0,%1,%2,%3};" \
    : "+f"((c)[0]), "+f"((c)[1]), "+f"((c)[2]), "+f"((c)[3]) \
    : "r"((a)[0]), "r"((a)[1]), "r"((a)[2]), "r"((a)[3]), "r"(b0), "r"(b1))

#define CPA(dst, src, sz) asm volatile( \
    "cp.async.cg.shared.global [%0], [%1], 16, %2;" :: "r"(dst), "l"(src), "r"(sz))

// ---------------- conversion kernels ----------------
// batched hi-only split: x (4096 blk), Wz (2048), dt_w (4096), out_w (2048)
__global__ void convert_batch(const float* __restrict__ x, const float* __restrict__ wz,
                              const float* __restrict__ dtw, const float* __restrict__ ow) {
    int b = blockIdx.x;
    const float* in;
    __half* h;
    int i;
    if (b < 4096)        { in = x;   h = g_xh;  i = b * 256 + threadIdx.x; }
    else if (b < 6144)   { in = wz;  h = g_wzh; i = (b - 4096) * 256 + threadIdx.x; }
    else if (b < 10240)  { in = dtw; h = g_dwh; i = (b - 6144) * 256 + threadIdx.x; }
    else                 { in = ow;  h = g_owh; i = (b - 10240) * 256 + threadIdx.x; }
    float4 v = reinterpret_cast<const float4*>(in)[i];
    reinterpret_cast<__half2*>(h)[2 * i]     = __floats2half2_rn(v.x, v.y);
    reinterpret_cast<__half2*>(h)[2 * i + 1] = __floats2half2_rn(v.z, v.w);
}

// transpose hi: in_proj rows 0..2047 ([2048,1024]) -> WxcT [1024,2048]
__global__ void tsplit_k(const float* __restrict__ w, __half* __restrict__ th) {
    __shared__ float t[32][33];
    int j0 = blockIdx.x * 32, i0 = blockIdx.y * 32;
    int tx = threadIdx.x & 31, ty4 = threadIdx.x >> 5;
#pragma unroll
    for (int s = 0; s < 4; s++) {
        int ty = ty4 + s * 8;
        t[ty][tx] = w[(size_t)(i0 + ty) * DMODEL + j0 + tx];
    }
    __syncthreads();
#pragma unroll
    for (int s = 0; s < 4; s++) {
        int ty = ty4 + s * 8;
        th[(size_t)(j0 + ty) * DINNER + i0 + tx] = __float2half_rn(t[tx][ty]);
    }
}

// conv_w [d][i][4] -> P_hi [tap][d][i]
__global__ void pack_split_k(const float* __restrict__ cw) {
    int g = blockIdx.x * 256 + threadIdx.x;
    float4 v = reinterpret_cast<const float4*>(cw)[g];
    float vv[4] = {v.x, v.y, v.z, v.w};
#pragma unroll
    for (int t = 0; t < 4; t++)
        g_Ph[(size_t)t * 4194304u + g] = __float2half_rn(vv[t]);
}

// ---------------- HMMA 1-pass GEMM: D = A @ B^T (both operands K-major) ----------------
// MODE 0: normal. MODE 1: conv-fold (A = x with per-1024-K-chunk row shift tap-3).
// EPI 0: none, 1: silu, 2: sigmoid+clip. HASB: +bias[n].
// OUT 0: f32 -> out. OUT 1: f16 -> oh. OUT 3: fold remap f16 -> oh (Mb layout).
#define KTILE   64
#define PITCH_B 144                // 64 halves data + 16B pad -> conflict-free ldmatrix
#define MATB    (128 * PITCH_B)    // 18432 B per matrix tile
#define NSTAGE  3
#define GSMEM   (NSTAGE * 2 * MATB)   // 110592 B (Ah, Bh) -> 2 CTAs/SM

template<int MODE, int EPI, bool HASB, int OUT>
__global__ __launch_bounds__(256, 2)
void tgemm(const __half* __restrict__ Ah, const __half* __restrict__ Bh,
           const float* __restrict__ bias, float* __restrict__ out,
           __half* __restrict__ oh,
           int M, int N, int K)
{
    extern __shared__ char sm_[];
    const int tid = threadIdx.x, lane = tid & 31, wid = tid >> 5;
    const int m0 = blockIdx.y * 128, n0 = blockIdx.x * 128;
    const uint32_t sb = smem_u32(sm_);

    const int wm = wid >> 2, wn = wid & 3;          // warp tile: 64(m) x 32(n)
    const int lr = lane & 15, lc8 = (lane >> 4) * 8;
    const uint32_t aoffH = (uint32_t)((wm * 64 + lr) * PITCH_B + lc8 * 2);
    const uint32_t boffH = (uint32_t)(MATB + (wn * 32 + lr) * PITCH_B + lc8 * 2);

    float acc[4][4][4] = {};

    // stage loader: 8 x 16B chunks per thread (Ah + Bh)
    auto ldst = [&](int kt) {
        const uint32_t st = sb + (kt % NSTAGE) * (2 * MATB);
        const int kb = kt * KTILE;
#pragma unroll
        for (int q = 0; q < 8; q++) {
            int cid = q * 256 + tid;
            int mat = cid >> 10, w = cid & 1023;
            int row = w >> 3, c = w & 7;
            uint32_t dst = st + mat * MATB + row * PITCH_B + c * 16;
            const __half* src;
            uint32_t sz = 16;
            if (mat == 0) {
                if (MODE == 1) {
                    int tap = kb >> 10, jb = kb & 1023, rg = m0 + row;
                    if (((rg & (SEQLEN - 1)) + tap - 3) < 0) { sz = 0; src = Ah; }
                    else src = Ah + (size_t)(rg + tap - 3) * DMODEL + jb + c * 8;
                } else {
                    src = Ah + (size_t)(m0 + row) * K + kb + c * 8;
                }
            } else {
                src = Bh + (size_t)(n0 + row) * K + kb + c * 8;
            }
            CPA(dst, src, sz);
        }
        asm volatile("cp.async.commit_group;" ::: "memory");
    };

    auto comp = [&](int s) {
        const uint32_t st = sb + s * (2 * MATB);
#pragma unroll
        for (int kk = 0; kk < KTILE / 16; kk++) {
            const uint32_t ko = kk * 32;            // 16 halves = 32 bytes
            uint32_t ah[4][4], bhf[2][4];
#pragma unroll
            for (int mt = 0; mt < 4; mt++) LDSM4(ah[mt], st + aoffH + mt * 16 * PITCH_B + ko);
#pragma unroll
            for (int np = 0; np < 2; np++) LDSM4(bhf[np], st + boffH + np * 16 * PITCH_B + ko);
#pragma unroll
            for (int mt = 0; mt < 4; mt++)
#pragma unroll
                for (int nt = 0; nt < 4; nt++)
                    MMAF32(acc[mt][nt], ah[mt], bhf[nt >> 1][nt & 1], bhf[nt >> 1][2 + (nt & 1)]);
        }
    };

    const int nk = K / KTILE;
    ldst(0);
    ldst(1);
    for (int kt = 0; kt < nk; kt++) {
        if (kt + 1 < nk) asm volatile("cp.async.wait_group 1;" ::: "memory");
        else             asm volatile("cp.async.wait_group 0;" ::: "memory");
        __syncthreads();
        if (kt + 2 < nk) ldst(kt + 2);
        comp(kt % NSTAGE);
    }

    // epilogue from register accumulators
    const int g = lane >> 2, tg = lane & 3;
#pragma unroll
    for (int mt = 0; mt < 4; mt++) {
#pragma unroll
        for (int nt = 0; nt < 4; nt++) {
            const int col = n0 + wn * 32 + nt * 8 + tg * 2;
            float b0 = 0.f, b1 = 0.f;
            if (HASB) { b0 = bias[col]; b1 = bias[col + 1]; }
#pragma unroll
            for (int h = 0; h < 2; h++) {
                const int r = m0 + wm * 64 + mt * 16 + g + h * 8;
                float v0 = acc[mt][nt][2 * h + 0] + b0;
                float v1 = acc[mt][nt][2 * h + 1] + b1;
                if (EPI == 1) {
                    v0 = v0 / (1.f + __expf(-v0));
                    v1 = v1 / (1.f + __expf(-v1));
                } else if (EPI == 2) {
                    v0 = fminf(fmaxf(1.f / (1.f + __expf(-v0)), 1e-4f), 1.f);
                    v1 = fminf(fmaxf(1.f / (1.f + __expf(-v1)), 1e-4f), 1.f);
                }
                if (OUT == 3) {
                    // fold remap: m = tap*2048 + d  ->  Mb[d][tap*1024 + col], f16 only
                    size_t dst = (size_t)(r & 2047) * 4096 + (size_t)(r >> 11) * 1024 + col;
                    *reinterpret_cast<__half2*>(oh + dst) = __floats2half2_rn(v0, v1);
                } else if (OUT == 1) {
                    *reinterpret_cast<__half2*>(oh + (size_t)r * N + col) = __floats2half2_rn(v0, v1);
                } else {
                    *reinterpret_cast<float2*>(out + (size_t)r * N + col) = make_float2(v0, v1);
                }
            }
        }
    }
}

// ---------------- small B/C projection GEMM (reads f16 u) ----------------
__global__ __launch_bounds__(256)
void bc_gemm(const __half* __restrict__ uh, const float* __restrict__ Bw,
             const float* __restrict__ Cw)
{
    __shared__ float us[32][65];
    __shared__ float ws[32][65];
    const int tid  = threadIdx.x;
    const int row0 = blockIdx.x * 32;
    const int c  = tid & 31;
    const int rq = tid >> 5;
    float acc[4] = {0.f, 0.f, 0.f, 0.f};

    for (int kt = 0; kt < DINNER; kt += 64) {
        __syncthreads();
#pragma unroll
        for (int s = 0; s < 8; s++) {
            int e = tid + s * 256;
            int r = e >> 6, k = e & 63;
            us[r][k] = __half2float(uh[(size_t)(row0 + r) * DINNER + kt + k]);
            ws[r][k] = (r < 16) ? Bw[r * DINNER + kt + k]
                                : Cw[(r - 16) * DINNER + kt + k];
        }
        __syncthreads();
#pragma unroll 8
        for (int k = 0; k < 64; k++) {
            float wv = ws[c][k];
#pragma unroll
            for (int i = 0; i < 4; i++)
                acc[i] = fmaf(us[rq * 4 + i][k], wv, acc[i]);
        }
    }
#pragma unroll
    for (int i = 0; i < 4; i++) {
        int row = row0 + rq * 4 + i;
        if (c < 16) g_Bm[(size_t)row * DSTATE + c]        = acc[i];
        else        g_Cm[(size_t)row * DSTATE + (c - 16)] = acc[i];
    }
}

// ---------------- selective scan (f16 u/sz inputs, emits f16 y) ----------------
__global__ __launch_bounds__(512)
void scan_k(const __half* __restrict__ uh, const float* __restrict__ dt,
            const float* __restrict__ Bm, const float* __restrict__ Cm,
            const float* __restrict__ Alog, const float* __restrict__ Dp,
            const __half* __restrict__ szh, __half* __restrict__ yh)
{
    const int tid = threadIdx.x;
    const int b   = blockIdx.x >> 6;
    const int d0  = (blockIdx.x & 63) * 32;
    const int dl  = tid >> 4;
    const int n   = tid & 15;
    const int d   = d0 + dl;
    const float Areg = -expf(Alog[d * DSTATE + n]);
    const float Dreg = Dp[d];
    const size_t rowbase = (size_t)b * SEQLEN;
    float state = 0.f;

    __shared__ float dt_s[2][32][32];
    __shared__ float u_s [2][32][32];
    __shared__ float sz_s[2][32][32];
    __shared__ float B_s [2][32][16];
    __shared__ float C_s [2][32][16];
    __shared__ float y_s [32][32];

    auto stage = [&](int buf, int l0) {
#pragma unroll
        for (int s = 0; s < 2; s++) {
            int e = tid + s * 512;
            int ll = e >> 5, dd = e & 31;
            size_t g = (rowbase + l0 + ll) * DINNER + d0 + dd;
            dt_s[buf][ll][dd] = dt[g];
            u_s [buf][ll][dd] = __half2float(uh[g]);
            sz_s[buf][ll][dd] = __half2float(szh[g]);
        }
        {
            int ll = tid >> 4, nn = tid & 15;
            size_t g = (rowbase + l0 + ll) * DSTATE + nn;
            B_s[buf][ll][nn] = Bm[g];
            C_s[buf][ll][nn] = Cm[g];
        }
    };

    stage(0, 0);
    __syncthreads();
    int buf = 0;
    for (int t = 0; t < SEQLEN / 32; t++) {
        const int l0 = t * 32;
        if (t + 1 < SEQLEN / 32) stage(buf ^ 1, l0 + 32);
#pragma unroll 4
        for (int ll = 0; ll < 32; ll++) {
            float dtv = dt_s[buf][ll][dl];
            float uv  = u_s [buf][ll][dl];
            float Bn  = B_s [buf][ll][n];
            float Cn  = C_s [buf][ll][n];
            float arg = fminf(fmaxf(dtv * Areg, -5.f), 5.f);
            float dA  = __expf(arg);
            float dB  = dtv * uv * Bn;
            state = fmaf(dA, state, dB + 1e-6f);
            float v = state * Cn;
            v += __shfl_xor_sync(0xffffffffu, v, 8);
            v += __shfl_xor_sync(0xffffffffu, v, 4);
            v += __shfl_xor_sync(0xffffffffu, v, 2);
            v += __shfl_xor_sync(0xffffffffu, v, 1);
            if (n == 0) y_s[ll][dl] = v + Dreg * uv;
        }
        __syncthreads();
#pragma unroll
        for (int s = 0; s < 2; s++) {
            int e = tid + s * 512;
            int ll = e >> 5, dd = e & 31;
            size_t g = (rowbase + l0 + ll) * DINNER + d0 + dd;
            yh[g] = __float2half_rn(y_s[ll][dd] * sz_s[buf][ll][dd]);
        }
        __syncthreads();
        buf ^= 1;
    }
}

// ---------------- launch ----------------
extern "C" void kernel_launch(void* const* d_in, const int* in_sizes, int n_in,
                              void* d_out, int out_size)
{
    (void)in_sizes; (void)n_in; (void)out_size;
    const float* x       = (const float*)d_in[0];
    const float* in_proj = (const float*)d_in[1];
    const float* conv_w  = (const float*)d_in[2];
    const float* conv_b  = (const float*)d_in[3];
    const float* dt_w    = (const float*)d_in[4];
    const float* dt_b    = (const float*)d_in[5];
    const float* A_log   = (const float*)d_in[6];
    const float* Dp      = (const float*)d_in[7];
    const float* B_w     = (const float*)d_in[8];
    const float* C_w     = (const float*)d_in[9];
    const float* out_w   = (const float*)d_in[10];
    float* out = (float*)d_out;

    auto ga = [](const void* sym) { void* p; cudaGetSymbolAddress(&p, sym); return p; };
    __half* xh  = (__half*)ga(g_xh);
    __half* wzh = (__half*)ga(g_wzh);
    __half* wth = (__half*)ga(g_wth);
    __half* Ph  = (__half*)ga(g_Ph);
    __half* Mbh = (__half*)ga(g_Mbh);
    __half* dwh = (__half*)ga(g_dwh);
    __half* owh = (__half*)ga(g_owh);
    __half* uh  = (__half*)ga(g_uh);
    __half* sh  = (__half*)ga(g_sh);
    float*  dtp = (float*)ga(g_dt);
    __half* yh  = (__half*)ga(g_yh);
    float*  Bm  = (float*)ga(g_Bm);
    float*  Cm  = (float*)ga(g_Cm);

    cudaFuncSetAttribute(tgemm<0,0,false,3>, cudaFuncAttributeMaxDynamicSharedMemorySize, GSMEM);
    cudaFuncSetAttribute(tgemm<0,1,false,1>, cudaFuncAttributeMaxDynamicSharedMemorySize, GSMEM);
    cudaFuncSetAttribute(tgemm<1,0,true,1>,  cudaFuncAttributeMaxDynamicSharedMemorySize, GSMEM);
    cudaFuncSetAttribute(tgemm<0,2,true,0>,  cudaFuncAttributeMaxDynamicSharedMemorySize, GSMEM);
    cudaFuncSetAttribute(tgemm<0,0,false,0>, cudaFuncAttributeMaxDynamicSharedMemorySize, GSMEM);

    // conversions
    convert_batch<<<12288, 256>>>(x, in_proj + (size_t)DINNER * DMODEL, dt_w, out_w);
    tsplit_k<<<dim3(32, 64), 256>>>(in_proj, wth);                       // WxcT
    pack_split_k<<<16384, 256>>>(conv_w);                                // conv taps

    // fold: M_k = P_k @ Wxc (M=8192, N=1024, K=2048) -> writes Mbh directly (remap)
    tgemm<0,0,false,3><<<dim3(8, 64), 256, GSMEM>>>(
        Ph, wth, nullptr, nullptr, Mbh, 8192, 1024, 2048);

    // silu(z) = silu(x @ Wz^T) -> f16 sh
    tgemm<0,1,false,1><<<dim3(16, 32), 256, GSMEM>>>(
        xh, wzh, nullptr, nullptr, sh, NTOK, DINNER, DMODEL);

    // u = conv fold (shifted K=4096) + conv_b -> f16 uh only
    tgemm<1,0,true,1><<<dim3(16, 32), 256, GSMEM>>>(
        xh, Mbh, conv_b, nullptr, uh, NTOK, DINNER, 4 * DMODEL);

    // dt = clip(sigmoid(u @ dt_w^T + dt_b)) -> fp32
    tgemm<0,2,true,0><<<dim3(16, 32), 256, GSMEM>>>(
        uh, dwh, dt_b, dtp, nullptr, NTOK, DINNER, DINNER);

    // B/C projections (read f16 u)
    bc_gemm<<<NTOK / 32, 256>>>(uh, B_w, C_w);

    // selective scan -> yh (f16)
    scan_k<<<128, 512>>>(uh, dtp, Bm, Cm, A_log, Dp, sh, yh);

    // out = y @ out_w^T -> fp32 d_out
    tgemm<0,0,false,0><<<dim3(8, 32), 256, GSMEM>>>(
        yh, owh, nullptr, out, nullptr, NTOK, DMODEL, DINNER);
}

// round 10
// speedup vs baseline: 1.5187x; 1.5187x over previous
#include <cuda_runtime.h>
#include <cuda_fp16.h>
#include <math.h>
#include <stdint.h>

#define DMODEL 1024
#define DINNER 2048
#define DSTATE 16
#define SEQLEN 2048
#define NTOK   4096   /* BATCH * SEQLEN */

// ---------------- scratch (device globals; no runtime allocation) ----------------
__device__ __half g_xh [NTOK * DMODEL];
__device__ __half g_wzh[DINNER * DMODEL];
__device__ __half g_wth[DMODEL * DINNER];     // WxcT hi
__device__ __half g_Ph [4u * DINNER * DINNER];
__device__ __half g_Mbh[DINNER * 4 * DMODEL]; // folded conv weights, conv layout
__device__ __half g_dwh[DINNER * DINNER];
__device__ __half g_owh[DMODEL * DINNER];
__device__ float  g_u  [NTOK * DINNER];
__device__ __half g_uh [NTOK * DINNER];
__device__ float  g_s  [NTOK * DINNER];       // silu(z)
__device__ float  g_dt [NTOK * DINNER];
__device__ __half g_yh [NTOK * DINNER];
__device__ float  g_Bm [NTOK * DSTATE], g_Cm [NTOK * DSTATE];

// ---------------- helpers ----------------
__device__ __forceinline__ uint32_t smem_u32(const void* p) {
    uint32_t a;
    asm("{ .reg .u64 t; cvta.to.shared.u64 t, %1; cvt.u32.u64 %0, t; }" : "=r"(a) : "l"(p));
    return a;
}

#define LDSM4(r, a) asm volatile( \
    "ldmatrix.sync.aligned.m8n8.x4.shared.b16 {%0,%1,%2,%3}, [%4];" \
    : "=r"((r)[0]), "=r"((r)[1]), "=r"((r)[2]), "=r"((r)[3]) : "r"(a))

#define MMAF32(c, a, b0, b1) asm volatile( \
    "mma.sync.aligned.m16n8k16.row.col.f32.f16.f16.f32 " \
    "{%0,%1,%2,%3},{%4,%5,%6,%7},{%8,%9},{%0,%1,%2,%3};" \
    : "+f"((c)[0]), "+f"((c)[1]), "+f"((c)[2]), "+f"((c)[3]) \
    : "r"((a)[0]), "r"((a)[1]), "r"((a)[2]), "r"((a)[3]), "r"(b0), "r"(b1))

#define CPA(dst, src, sz) asm volatile( \
    "cp.async.cg.shared.global [%0], [%1], 16, %2;" :: "r"(dst), "l"(src), "r"(sz))

// ---------------- conversion kernels ----------------
// batched hi-only split: x (4096 blk), Wz (2048), dt_w (4096), out_w (2048)
__global__ void convert_batch(const float* __restrict__ x, const float* __restrict__ wz,
                              const float* __restrict__ dtw, const float* __restrict__ ow) {
    int b = blockIdx.x;
    const float* in;
    __half* h;
    int i;
    if (b < 4096)        { in = x;   h = g_xh;  i = b * 256 + threadIdx.x; }
    else if (b < 6144)   { in = wz;  h = g_wzh; i = (b - 4096) * 256 + threadIdx.x; }
    else if (b < 10240)  { in = dtw; h = g_dwh; i = (b - 6144) * 256 + threadIdx.x; }
    else                 { in = ow;  h = g_owh; i = (b - 10240) * 256 + threadIdx.x; }
    float4 v = reinterpret_cast<const float4*>(in)[i];
    reinterpret_cast<__half2*>(h)[2 * i]     = __floats2half2_rn(v.x, v.y);
    reinterpret_cast<__half2*>(h)[2 * i + 1] = __floats2half2_rn(v.z, v.w);
}

// transpose hi: in_proj rows 0..2047 ([2048,1024]) -> WxcT [1024,2048]
__global__ void tsplit_k(const float* __restrict__ w, __half* __restrict__ th) {
    __shared__ float t[32][33];
    int j0 = blockIdx.x * 32, i0 = blockIdx.y * 32;
    int tx = threadIdx.x & 31, ty4 = threadIdx.x >> 5;
#pragma unroll
    for (int s = 0; s < 4; s++) {
        int ty = ty4 + s * 8;
        t[ty][tx] = w[(size_t)(i0 + ty) * DMODEL + j0 + tx];
    }
    __syncthreads();
#pragma unroll
    for (int s = 0; s < 4; s++) {
        int ty = ty4 + s * 8;
        th[(size_t)(j0 + ty) * DINNER + i0 + tx] = __float2half_rn(t[tx][ty]);
    }
}

// conv_w [d][i][4] -> P_hi [tap][d][i]
__global__ void pack_split_k(const float* __restrict__ cw) {
    int g = blockIdx.x * 256 + threadIdx.x;
    float4 v = reinterpret_cast<const float4*>(cw)[g];
    float vv[4] = {v.x, v.y, v.z, v.w};
#pragma unroll
    for (int t = 0; t < 4; t++)
        g_Ph[(size_t)t * 4194304u + g] = __float2half_rn(vv[t]);
}

// ---------------- HMMA 1-pass GEMM: D = A @ B^T (both operands K-major) ----------------
// MODE 0: normal. MODE 1: conv-fold (A = x with per-1024-K-chunk row shift tap-3).
// MODE 2: fold-output remap — write f16 only, to Mb[d][tap*1024+col] with m=tap*2048+d.
// EPI 0: none, 1: silu, 2: sigmoid+clip. HASB: +bias[n]. HILO: also write f16 hi of result.
#define KTILE   64
#define PITCH_B 144                // 64 halves data + 16B pad -> conflict-free ldmatrix
#define MATB    (128 * PITCH_B)    // 18432 B per matrix tile
#define NSTAGE  3
#define GSMEM   (NSTAGE * 2 * MATB)   // 110592 B (Ah, Bh) -> 2 CTAs/SM

template<int MODE, int EPI, bool HASB, bool HILO>
__global__ __launch_bounds__(256, 2)
void tgemm(const __half* __restrict__ Ah, const __half* __restrict__ Bh,
           const float* __restrict__ bias, float* __restrict__ out,
           __half* __restrict__ oh,
           int M, int N, int K)
{
    extern __shared__ char sm_[];
    const int tid = threadIdx.x, lane = tid & 31, wid = tid >> 5;
    const int m0 = blockIdx.y * 128, n0 = blockIdx.x * 128;
    const uint32_t sb = smem_u32(sm_);

    const int wm = wid >> 2, wn = wid & 3;          // warp tile: 64(m) x 32(n)
    const int lr = lane & 15, lc8 = (lane >> 4) * 8;
    const uint32_t aoffH = (uint32_t)((wm * 64 + lr) * PITCH_B + lc8 * 2);
    const uint32_t boffH = (uint32_t)(MATB + (wn * 32 + lr) * PITCH_B + lc8 * 2);

    float acc[4][4][4] = {};

    // stage loader: 8 x 16B chunks per thread (Ah + Bh)
    auto ldst = [&](int kt) {
        const uint32_t st = sb + (kt % NSTAGE) * (2 * MATB);
        const int kb = kt * KTILE;
#pragma unroll
        for (int q = 0; q < 8; q++) {
            int cid = q * 256 + tid;
            int mat = cid >> 10, w = cid & 1023;
            int row = w >> 3, c = w & 7;
            uint32_t dst = st + mat * MATB + row * PITCH_B + c * 16;
            const __half* src;
            uint32_t sz = 16;
            if (mat == 0) {
                if (MODE == 1) {
                    int tap = kb >> 10, jb = kb & 1023, rg = m0 + row;
                    if (((rg & (SEQLEN - 1)) + tap - 3) < 0) { sz = 0; src = Ah; }
                    else src = Ah + (size_t)(rg + tap - 3) * DMODEL + jb + c * 8;
                } else {
                    src = Ah + (size_t)(m0 + row) * K + kb + c * 8;
                }
            } else {
                src = Bh + (size_t)(n0 + row) * K + kb + c * 8;
            }
            CPA(dst, src, sz);
        }
        asm volatile("cp.async.commit_group;" ::: "memory");
    };

    auto comp = [&](int s) {
        const uint32_t st = sb + s * (2 * MATB);
#pragma unroll
        for (int kk = 0; kk < KTILE / 16; kk++) {
            const uint32_t ko = kk * 32;            // 16 halves = 32 bytes
            uint32_t ah[4][4], bhf[2][4];
#pragma unroll
            for (int mt = 0; mt < 4; mt++) LDSM4(ah[mt], st + aoffH + mt * 16 * PITCH_B + ko);
#pragma unroll
            for (int np = 0; np < 2; np++) LDSM4(bhf[np], st + boffH + np * 16 * PITCH_B + ko);
#pragma unroll
            for (int mt = 0; mt < 4; mt++)
#pragma unroll
                for (int nt = 0; nt < 4; nt++)
                    MMAF32(acc[mt][nt], ah[mt], bhf[nt >> 1][nt & 1], bhf[nt >> 1][2 + (nt & 1)]);
        }
    };

    const int nk = K / KTILE;
    ldst(0);
    ldst(1);
    for (int kt = 0; kt < nk; kt++) {
        if (kt + 1 < nk) asm volatile("cp.async.wait_group 1;" ::: "memory");
        else             asm volatile("cp.async.wait_group 0;" ::: "memory");
        __syncthreads();
        if (kt + 2 < nk) ldst(kt + 2);
        comp(kt % NSTAGE);
    }

    // epilogue from register accumulators
    const int g = lane >> 2, tg = lane & 3;
#pragma unroll
    for (int mt = 0; mt < 4; mt++) {
#pragma unroll
        for (int nt = 0; nt < 4; nt++) {
            const int col = n0 + wn * 32 + nt * 8 + tg * 2;
            float b0 = 0.f, b1 = 0.f;
            if (HASB) { b0 = bias[col]; b1 = bias[col + 1]; }
#pragma unroll
            for (int h = 0; h < 2; h++) {
                const int r = m0 + wm * 64 + mt * 16 + g + h * 8;
                float v0 = acc[mt][nt][2 * h + 0] + b0;
                float v1 = acc[mt][nt][2 * h + 1] + b1;
                if (EPI == 1) {
                    v0 = v0 / (1.f + __expf(-v0));
                    v1 = v1 / (1.f + __expf(-v1));
                } else if (EPI == 2) {
                    v0 = fminf(fmaxf(1.f / (1.f + __expf(-v0)), 1e-4f), 1.f);
                    v1 = fminf(fmaxf(1.f / (1.f + __expf(-v1)), 1e-4f), 1.f);
                }
                if (MODE == 2) {
                    // fold remap: m = tap*2048 + d  ->  Mb[d][tap*1024 + col], f16 only
                    size_t dst = (size_t)(r & 2047) * 4096 + (size_t)(r >> 11) * 1024 + col;
                    *reinterpret_cast<__half2*>(oh + dst) = __floats2half2_rn(v0, v1);
                } else {
                    *reinterpret_cast<float2*>(out + (size_t)r * N + col) = make_float2(v0, v1);
                    if (HILO)
                        *reinterpret_cast<__half2*>(oh + (size_t)r * N + col) = __floats2half2_rn(v0, v1);
                }
            }
        }
    }
}

// ---------------- small B/C projection GEMM ----------------
__global__ __launch_bounds__(256)
void bc_gemm(const float* __restrict__ u, const float* __restrict__ Bw,
             const float* __restrict__ Cw)
{
    __shared__ float us[32][65];
    __shared__ float ws[32][65];
    const int tid  = threadIdx.x;
    const int row0 = blockIdx.x * 32;
    const int c  = tid & 31;
    const int rq = tid >> 5;
    float acc[4] = {0.f, 0.f, 0.f, 0.f};

    for (int kt = 0; kt < DINNER; kt += 64) {
        __syncthreads();
#pragma unroll
        for (int s = 0; s < 8; s++) {
            int e = tid + s * 256;
            int r = e >> 6, k = e & 63;
            us[r][k] = u[(size_t)(row0 + r) * DINNER + kt + k];
            ws[r][k] = (r < 16) ? Bw[r * DINNER + kt + k]
                                : Cw[(r - 16) * DINNER + kt + k];
        }
        __syncthreads();
#pragma unroll 8
        for (int k = 0; k < 64; k++) {
            float wv = ws[c][k];
#pragma unroll
            for (int i = 0; i < 4; i++)
                acc[i] = fmaf(us[rq * 4 + i][k], wv, acc[i]);
        }
    }
#pragma unroll
    for (int i = 0; i < 4; i++) {
        int row = row0 + rq * 4 + i;
        if (c < 16) g_Bm[(size_t)row * DSTATE + c]        = acc[i];
        else        g_Cm[(size_t)row * DSTATE + (c - 16)] = acc[i];
    }
}

// ---------------- selective scan (emits f16 hi of y for the out GEMM) ----------------
__global__ __launch_bounds__(512)
void scan_k(const float* __restrict__ u, const float* __restrict__ dt,
            const float* __restrict__ Bm, const float* __restrict__ Cm,
            const float* __restrict__ Alog, const float* __restrict__ Dp,
            const float* __restrict__ sz, __half* __restrict__ yh)
{
    const int tid = threadIdx.x;
    const int b   = blockIdx.x >> 6;
    const int d0  = (blockIdx.x & 63) * 32;
    const int dl  = tid >> 4;
    const int n   = tid & 15;
    const int d   = d0 + dl;
    const float Areg = -expf(Alog[d * DSTATE + n]);
    const float Dreg = Dp[d];
    const size_t rowbase = (size_t)b * SEQLEN;
    float state = 0.f;

    __shared__ float dt_s[2][32][32];
    __shared__ float u_s [2][32][32];
    __shared__ float sz_s[2][32][32];
    __shared__ float B_s [2][32][16];
    __shared__ float C_s [2][32][16];
    __shared__ float y_s [32][32];

    auto stage = [&](int buf, int l0) {
#pragma unroll
        for (int s = 0; s < 2; s++) {
            int e = tid + s * 512;
            int ll = e >> 5, dd = e & 31;
            size_t g = (rowbase + l0 + ll) * DINNER + d0 + dd;
            dt_s[buf][ll][dd] = dt[g];
            u_s [buf][ll][dd] = u[g];
            sz_s[buf][ll][dd] = sz[g];
        }
        {
            int ll = tid >> 4, nn = tid & 15;
            size_t g = (rowbase + l0 + ll) * DSTATE + nn;
            B_s[buf][ll][nn] = Bm[g];
            C_s[buf][ll][nn] = Cm[g];
        }
    };

    stage(0, 0);
    __syncthreads();
    int buf = 0;
    for (int t = 0; t < SEQLEN / 32; t++) {
        const int l0 = t * 32;
        if (t + 1 < SEQLEN / 32) stage(buf ^ 1, l0 + 32);
#pragma unroll 4
        for (int ll = 0; ll < 32; ll++) {
            float dtv = dt_s[buf][ll][dl];
            float uv  = u_s [buf][ll][dl];
            float Bn  = B_s [buf][ll][n];
            float Cn  = C_s [buf][ll][n];
            float arg = fminf(fmaxf(dtv * Areg, -5.f), 5.f);
            float dA  = __expf(arg);
            float dB  = dtv * uv * Bn;
            state = fmaf(dA, state, dB + 1e-6f);
            float v = state * Cn;
            v += __shfl_xor_sync(0xffffffffu, v, 8);
            v += __shfl_xor_sync(0xffffffffu, v, 4);
            v += __shfl_xor_sync(0xffffffffu, v, 2);
            v += __shfl_xor_sync(0xffffffffu, v, 1);
            if (n == 0) y_s[ll][dl] = v + Dreg * uv;
        }
        __syncthreads();
#pragma unroll
        for (int s = 0; s < 2; s++) {
            int e = tid + s * 512;
            int ll = e >> 5, dd = e & 31;
            size_t g = (rowbase + l0 + ll) * DINNER + d0 + dd;
            yh[g] = __float2half_rn(y_s[ll][dd] * sz_s[buf][ll][dd]);
        }
        __syncthreads();
        buf ^= 1;
    }
}

// ---------------- launch ----------------
extern "C" void kernel_launch(void* const* d_in, const int* in_sizes, int n_in,
                              void* d_out, int out_size)
{
    (void)in_sizes; (void)n_in; (void)out_size;
    const float* x       = (const float*)d_in[0];
    const float* in_proj = (const float*)d_in[1];
    const float* conv_w  = (const float*)d_in[2];
    const float* conv_b  = (const float*)d_in[3];
    const float* dt_w    = (const float*)d_in[4];
    const float* dt_b    = (const float*)d_in[5];
    const float* A_log   = (const float*)d_in[6];
    const float* Dp      = (const float*)d_in[7];
    const float* B_w     = (const float*)d_in[8];
    const float* C_w     = (const float*)d_in[9];
    const float* out_w   = (const float*)d_in[10];
    float* out = (float*)d_out;

    auto ga = [](const void* sym) { void* p; cudaGetSymbolAddress(&p, sym); return p; };
    __half* xh  = (__half*)ga(g_xh);
    __half* wzh = (__half*)ga(g_wzh);
    __half* wth = (__half*)ga(g_wth);
    __half* Ph  = (__half*)ga(g_Ph);
    __half* Mbh = (__half*)ga(g_Mbh);
    __half* dwh = (__half*)ga(g_dwh);
    __half* owh = (__half*)ga(g_owh);
    float* u  = (float*)ga(g_u);
    __half* uh = (__half*)ga(g_uh);
    float* s  = (float*)ga(g_s);
    float* dtp = (float*)ga(g_dt);
    __half* yh = (__half*)ga(g_yh);
    float* Bm = (float*)ga(g_Bm);
    float* Cm = (float*)ga(g_Cm);

    cudaFuncSetAttribute(tgemm<2,0,false,true>,  cudaFuncAttributeMaxDynamicSharedMemorySize, GSMEM);
    cudaFuncSetAttribute(tgemm<0,1,false,false>, cudaFuncAttributeMaxDynamicSharedMemorySize, GSMEM);
    cudaFuncSetAttribute(tgemm<1,0,true,true>,   cudaFuncAttributeMaxDynamicSharedMemorySize, GSMEM);
    cudaFuncSetAttribute(tgemm<0,2,true,false>,  cudaFuncAttributeMaxDynamicSharedMemorySize, GSMEM);
    cudaFuncSetAttribute(tgemm<0,0,false,false>, cudaFuncAttributeMaxDynamicSharedMemorySize, GSMEM);

    // conversions (merged elementwise splits + transpose + conv pack)
    convert_batch<<<12288, 256>>>(x, in_proj + (size_t)DINNER * DMODEL, dt_w, out_w);
    tsplit_k<<<dim3(32, 64), 256>>>(in_proj, wth);                       // WxcT
    pack_split_k<<<16384, 256>>>(conv_w);                                // conv taps

    // fold: M_k = P_k @ Wxc (M=8192, N=1024, K=2048) -> writes Mbh directly (remap)
    tgemm<2,0,false,true><<<dim3(8, 64), 256, GSMEM>>>(
        Ph, wth, nullptr, nullptr, Mbh, 8192, 1024, 2048);

    // silu(z) = silu(x @ Wz^T)
    tgemm<0,1,false,false><<<dim3(16, 32), 256, GSMEM>>>(
        xh, wzh, nullptr, s, nullptr, NTOK, DINNER, DMODEL);

    // u = conv fold (shifted K=4096) + conv_b; emits f16 hi of u
    tgemm<1,0,true,true><<<dim3(16, 32), 256, GSMEM>>>(
        xh, Mbh, conv_b, u, uh, NTOK, DINNER, 4 * DMODEL);

    // dt = clip(sigmoid(u @ dt_w^T + dt_b))
    tgemm<0,2,true,false><<<dim3(16, 32), 256, GSMEM>>>(
        uh, dwh, dt_b, dtp, nullptr, NTOK, DINNER, DINNER);

    // B/C projections
    bc_gemm<<<NTOK / 32, 256>>>(u, B_w, C_w);

    // selective scan -> yh (f16)
    scan_k<<<128, 512>>>(u, dtp, Bm, Cm, A_log, Dp, s, yh);

    // out = y @ out_w^T
    tgemm<0,0,false,false><<<dim3(8, 32), 256, GSMEM>>>(
        yh, owh, nullptr, out, nullptr, NTOK, DMODEL, DINNER);
}

// round 11
// speedup vs baseline: 1.5316x; 1.0085x over previous
#include <cuda_runtime.h>
#include <cuda_fp16.h>
#include <math.h>
#include <stdint.h>

#define DMODEL 1024
#define DINNER 2048
#define DSTATE 16
#define SEQLEN 2048
#define NTOK   4096   /* BATCH * SEQLEN */

// ---------------- scratch (device globals; no runtime allocation) ----------------
__device__ __half g_xh [NTOK * DMODEL];
__device__ __half g_wzh[DINNER * DMODEL];
__device__ __half g_wth[DMODEL * DINNER];     // WxcT hi
__device__ __half g_Ph [4u * DINNER * DINNER];
__device__ __half g_Mbh[DINNER * 4 * DMODEL]; // folded conv weights, conv layout
__device__ __half g_dwh[DINNER * DINNER];
__device__ __half g_owh[DMODEL * DINNER];
__device__ __half g_uh [NTOK * DINNER];       // conv output (f16 only)
__device__ __half g_sh [NTOK * DINNER];       // silu(z) (f16 only)
__device__ float  g_dt [NTOK * DINNER];       // dt kept fp32 (exp-argument sensitivity)
__device__ __half g_yh [NTOK * DINNER];
__device__ float  g_Bm [NTOK * DSTATE], g_Cm [NTOK * DSTATE];

// ---------------- helpers ----------------
__device__ __forceinline__ uint32_t smem_u32(const void* p) {
    uint32_t a;
    asm("{ .reg .u64 t; cvta.to.shared.u64 t, %1; cvt.u32.u64 %0, t; }" : "=r"(a) : "l"(p));
    return a;
}

#define LDSM4(r, a) asm volatile( \
    "ldmatrix.sync.aligned.m8n8.x4.shared.b16 {%0,%1,%2,%3}, [%4];" \
    : "=r"((r)[0]), "=r"((r)[1]), "=r"((r)[2]), "=r"((r)[3]) : "r"(a))

#define MMAF32(c, a, b0, b1) asm volatile( \
    "mma.sync.aligned.m16n8k16.row.col.f32.f16.f16.f32 " \
    "{%0,%1,%2,%3},{%4,%5,%6,%7},{%8,%9},{%0,%1,%2,%3};" \
    : "+f"((c)[0]), "+f"((c)[1]), "+f"((c)[2]), "+f"((c)[3]) \
    : "r"((a)[0]), "r"((a)[1]), "r"((a)[2]), "r"((a)[3]), "r"(b0), "r"(b1))

#define CPA(dst, src, sz) asm volatile( \
    "cp.async.cg.shared.global [%0], [%1], 16, %2;" :: "r"(dst), "l"(src), "r"(sz))

// ---------------- conversion kernels ----------------
// batched hi-only split: x (4096 blk), Wz (2048), dt_w (4096), out_w (2048)
__global__ void convert_batch(const float* __restrict__ x, const float* __restrict__ wz,
                              const float* __restrict__ dtw, const float* __restrict__ ow) {
    int b = blockIdx.x;
    const float* in;
    __half* h;
    int i;
    if (b < 4096)        { in = x;   h = g_xh;  i = b * 256 + threadIdx.x; }
    else if (b < 6144)   { in = wz;  h = g_wzh; i = (b - 4096) * 256 + threadIdx.x; }
    else if (b < 10240)  { in = dtw; h = g_dwh; i = (b - 6144) * 256 + threadIdx.x; }
    else                 { in = ow;  h = g_owh; i = (b - 10240) * 256 + threadIdx.x; }
    float4 v = reinterpret_cast<const float4*>(in)[i];
    reinterpret_cast<__half2*>(h)[2 * i]     = __floats2half2_rn(v.x, v.y);
    reinterpret_cast<__half2*>(h)[2 * i + 1] = __floats2half2_rn(v.z, v.w);
}

// transpose hi: in_proj rows 0..2047 ([2048,1024]) -> WxcT [1024,2048]
__global__ void tsplit_k(const float* __restrict__ w, __half* __restrict__ th) {
    __shared__ float t[32][33];
    int j0 = blockIdx.x * 32, i0 = blockIdx.y * 32;
    int tx = threadIdx.x & 31, ty4 = threadIdx.x >> 5;
#pragma unroll
    for (int s = 0; s < 4; s++) {
        int ty = ty4 + s * 8;
        t[ty][tx] = w[(size_t)(i0 + ty) * DMODEL + j0 + tx];
    }
    __syncthreads();
#pragma unroll
    for (int s = 0; s < 4; s++) {
        int ty = ty4 + s * 8;
        th[(size_t)(j0 + ty) * DINNER + i0 + tx] = __float2half_rn(t[tx][ty]);
    }
}

// conv_w [d][i][4] -> P_hi [tap][d][i]
__global__ void pack_split_k(const float* __restrict__ cw) {
    int g = blockIdx.x * 256 + threadIdx.x;
    float4 v = reinterpret_cast<const float4*>(cw)[g];
    float vv[4] = {v.x, v.y, v.z, v.w};
#pragma unroll
    for (int t = 0; t < 4; t++)
        g_Ph[(size_t)t * 4194304u + g] = __float2half_rn(vv[t]);
}

// ---------------- HMMA 1-pass GEMM: D = A @ B^T (both operands K-major) ----------------
// MODE 0: normal. MODE 1: conv-fold (A = x with per-1024-K-chunk row shift tap-3).
// EPI 0: none, 1: silu, 2: sigmoid+clip. HASB: +bias[n].
// OUT 0: f32 -> out. OUT 1: f16 -> oh. OUT 3: fold remap f16 -> oh (Mb layout).
#define KTILE   64
#define PITCH_B 144                // 64 halves data + 16B pad -> conflict-free ldmatrix
#define MATB    (128 * PITCH_B)    // 18432 B per matrix tile
#define NSTAGE  3
#define GSMEM   (NSTAGE * 2 * MATB)   // 110592 B (Ah, Bh) -> 2 CTAs/SM

template<int MODE, int EPI, bool HASB, int OUT>
__global__ __launch_bounds__(256, 2)
void tgemm(const __half* __restrict__ Ah, const __half* __restrict__ Bh,
           const float* __restrict__ bias, float* __restrict__ out,
           __half* __restrict__ oh,
           int M, int N, int K)
{
    extern __shared__ char sm_[];
    const int tid = threadIdx.x, lane = tid & 31, wid = tid >> 5;
    const int m0 = blockIdx.y * 128, n0 = blockIdx.x * 128;
    const uint32_t sb = smem_u32(sm_);

    const int wm = wid >> 2, wn = wid & 3;          // warp tile: 64(m) x 32(n)
    const int lr = lane & 15, lc8 = (lane >> 4) * 8;
    const uint32_t aoffH = (uint32_t)((wm * 64 + lr) * PITCH_B + lc8 * 2);
    const uint32_t boffH = (uint32_t)(MATB + (wn * 32 + lr) * PITCH_B + lc8 * 2);

    float acc[4][4][4] = {};

    // stage loader: 8 x 16B chunks per thread (Ah + Bh)
    auto ldst = [&](int kt) {
        const uint32_t st = sb + (kt % NSTAGE) * (2 * MATB);
        const int kb = kt * KTILE;
#pragma unroll
        for (int q = 0; q < 8; q++) {
            int cid = q * 256 + tid;
            int mat = cid >> 10, w = cid & 1023;
            int row = w >> 3, c = w & 7;
            uint32_t dst = st + mat * MATB + row * PITCH_B + c * 16;
            const __half* src;
            uint32_t sz = 16;
            if (mat == 0) {
                if (MODE == 1) {
                    int tap = kb >> 10, jb = kb & 1023, rg = m0 + row;
                    if (((rg & (SEQLEN - 1)) + tap - 3) < 0) { sz = 0; src = Ah; }
                    else src = Ah + (size_t)(rg + tap - 3) * DMODEL + jb + c * 8;
                } else {
                    src = Ah + (size_t)(m0 + row) * K + kb + c * 8;
                }
            } else {
                src = Bh + (size_t)(n0 + row) * K + kb + c * 8;
            }
            CPA(dst, src, sz);
        }
        asm volatile("cp.async.commit_group;" ::: "memory");
    };

    auto comp = [&](int s) {
        const uint32_t st = sb + s * (2 * MATB);
#pragma unroll
        for (int kk = 0; kk < KTILE / 16; kk++) {
            const uint32_t ko = kk * 32;            // 16 halves = 32 bytes
            uint32_t ah[4][4], bhf[2][4];
#pragma unroll
            for (int mt = 0; mt < 4; mt++) LDSM4(ah[mt], st + aoffH + mt * 16 * PITCH_B + ko);
#pragma unroll
            for (int np = 0; np < 2; np++) LDSM4(bhf[np], st + boffH + np * 16 * PITCH_B + ko);
#pragma unroll
            for (int mt = 0; mt < 4; mt++)
#pragma unroll
                for (int nt = 0; nt < 4; nt++)
                    MMAF32(acc[mt][nt], ah[mt], bhf[nt >> 1][nt & 1], bhf[nt >> 1][2 + (nt & 1)]);
        }
    };

    const int nk = K / KTILE;
    ldst(0);
    ldst(1);
    for (int kt = 0; kt < nk; kt++) {
        if (kt + 1 < nk) asm volatile("cp.async.wait_group 1;" ::: "memory");
        else             asm volatile("cp.async.wait_group 0;" ::: "memory");
        __syncthreads();
        if (kt + 2 < nk) ldst(kt + 2);
        comp(kt % NSTAGE);
    }

    // epilogue from register accumulators
    const int g = lane >> 2, tg = lane & 3;
#pragma unroll
    for (int mt = 0; mt < 4; mt++) {
#pragma unroll
        for (int nt = 0; nt < 4; nt++) {
            const int col = n0 + wn * 32 + nt * 8 + tg * 2;
            float b0 = 0.f, b1 = 0.f;
            if (HASB) { b0 = bias[col]; b1 = bias[col + 1]; }
#pragma unroll
            for (int h = 0; h < 2; h++) {
                const int r = m0 + wm * 64 + mt * 16 + g + h * 8;
                float v0 = acc[mt][nt][2 * h + 0] + b0;
                float v1 = acc[mt][nt][2 * h + 1] + b1;
                if (EPI == 1) {
                    v0 = v0 / (1.f + __expf(-v0));
                    v1 = v1 / (1.f + __expf(-v1));
                } else if (EPI == 2) {
                    v0 = fminf(fmaxf(1.f / (1.f + __expf(-v0)), 1e-4f), 1.f);
                    v1 = fminf(fmaxf(1.f / (1.f + __expf(-v1)), 1e-4f), 1.f);
                }
                if (OUT == 3) {
                    // fold remap: m = tap*2048 + d  ->  Mb[d][tap*1024 + col], f16 only
                    size_t dst = (size_t)(r & 2047) * 4096 + (size_t)(r >> 11) * 1024 + col;
                    *reinterpret_cast<__half2*>(oh + dst) = __floats2half2_rn(v0, v1);
                } else if (OUT == 1) {
                    *reinterpret_cast<__half2*>(oh + (size_t)r * N + col) = __floats2half2_rn(v0, v1);
                } else {
                    *reinterpret_cast<float2*>(out + (size_t)r * N + col) = make_float2(v0, v1);
                }
            }
        }
    }
}

// ---------------- small B/C projection GEMM (reads f16 u) ----------------
__global__ __launch_bounds__(256)
void bc_gemm(const __half* __restrict__ uh, const float* __restrict__ Bw,
             const float* __restrict__ Cw)
{
    __shared__ float us[32][65];
    __shared__ float ws[32][65];
    const int tid  = threadIdx.x;
    const int row0 = blockIdx.x * 32;
    const int c  = tid & 31;
    const int rq = tid >> 5;
    float acc[4] = {0.f, 0.f, 0.f, 0.f};

    for (int kt = 0; kt < DINNER; kt += 64) {
        __syncthreads();
#pragma unroll
        for (int s = 0; s < 8; s++) {
            int e = tid + s * 256;
            int r = e >> 6, k = e & 63;
            us[r][k] = __half2float(uh[(size_t)(row0 + r) * DINNER + kt + k]);
            ws[r][k] = (r < 16) ? Bw[r * DINNER + kt + k]
                                : Cw[(r - 16) * DINNER + kt + k];
        }
        __syncthreads();
#pragma unroll 8
        for (int k = 0; k < 64; k++) {
            float wv = ws[c][k];
#pragma unroll
            for (int i = 0; i < 4; i++)
                acc[i] = fmaf(us[rq * 4 + i][k], wv, acc[i]);
        }
    }
#pragma unroll
    for (int i = 0; i < 4; i++) {
        int row = row0 + rq * 4 + i;
        if (c < 16) g_Bm[(size_t)row * DSTATE + c]        = acc[i];
        else        g_Cm[(size_t)row * DSTATE + (c - 16)] = acc[i];
    }
}

// ---------------- selective scan (f16 u/sz inputs, emits f16 y) ----------------
__global__ __launch_bounds__(512)
void scan_k(const __half* __restrict__ uh, const float* __restrict__ dt,
            const float* __restrict__ Bm, const float* __restrict__ Cm,
            const float* __restrict__ Alog, const float* __restrict__ Dp,
            const __half* __restrict__ szh, __half* __restrict__ yh)
{
    const int tid = threadIdx.x;
    const int b   = blockIdx.x >> 6;
    const int d0  = (blockIdx.x & 63) * 32;
    const int dl  = tid >> 4;
    const int n   = tid & 15;
    const int d   = d0 + dl;
    const float Areg = -expf(Alog[d * DSTATE + n]);
    const float Dreg = Dp[d];
    const size_t rowbase = (size_t)b * SEQLEN;
    float state = 0.f;

    __shared__ float dt_s[2][32][32];
    __shared__ float u_s [2][32][32];
    __shared__ float sz_s[2][32][32];
    __shared__ float B_s [2][32][16];
    __shared__ float C_s [2][32][16];
    __shared__ float y_s [32][32];

    auto stage = [&](int buf, int l0) {
#pragma unroll
        for (int s = 0; s < 2; s++) {
            int e = tid + s * 512;
            int ll = e >> 5, dd = e & 31;
            size_t g = (rowbase + l0 + ll) * DINNER + d0 + dd;
            dt_s[buf][ll][dd] = dt[g];
            u_s [buf][ll][dd] = __half2float(uh[g]);
            sz_s[buf][ll][dd] = __half2float(szh[g]);
        }
        {
            int ll = tid >> 4, nn = tid & 15;
            size_t g = (rowbase + l0 + ll) * DSTATE + nn;
            B_s[buf][ll][nn] = Bm[g];
            C_s[buf][ll][nn] = Cm[g];
        }
    };

    stage(0, 0);
    __syncthreads();
    int buf = 0;
    for (int t = 0; t < SEQLEN / 32; t++) {
        const int l0 = t * 32;
        if (t + 1 < SEQLEN / 32) stage(buf ^ 1, l0 + 32);
#pragma unroll 4
        for (int ll = 0; ll < 32; ll++) {
            float dtv = dt_s[buf][ll][dl];
            float uv  = u_s [buf][ll][dl];
            float Bn  = B_s [buf][ll][n];
            float Cn  = C_s [buf][ll][n];
            float arg = fminf(fmaxf(dtv * Areg, -5.f), 5.f);
            float dA  = __expf(arg);
            float dB  = dtv * uv * Bn;
            state = fmaf(dA, state, dB + 1e-6f);
            float v = state * Cn;
            v += __shfl_xor_sync(0xffffffffu, v, 8);
            v += __shfl_xor_sync(0xffffffffu, v, 4);
            v += __shfl_xor_sync(0xffffffffu, v, 2);
            v += __shfl_xor_sync(0xffffffffu, v, 1);
            if (n == 0) y_s[ll][dl] = v + Dreg * uv;
        }
        __syncthreads();
#pragma unroll
        for (int s = 0; s < 2; s++) {
            int e = tid + s * 512;
            int ll = e >> 5, dd = e & 31;
            size_t g = (rowbase + l0 + ll) * DINNER + d0 + dd;
            yh[g] = __float2half_rn(y_s[ll][dd] * sz_s[buf][ll][dd]);
        }
        __syncthreads();
        buf ^= 1;
    }
}

// ---------------- launch ----------------
extern "C" void kernel_launch(void* const* d_in, const int* in_sizes, int n_in,
                              void* d_out, int out_size)
{
    (void)in_sizes; (void)n_in; (void)out_size;
    const float* x       = (const float*)d_in[0];
    const float* in_proj = (const float*)d_in[1];
    const float* conv_w  = (const float*)d_in[2];
    const float* conv_b  = (const float*)d_in[3];
    const float* dt_w    = (const float*)d_in[4];
    const float* dt_b    = (const float*)d_in[5];
    const float* A_log   = (const float*)d_in[6];
    const float* Dp      = (const float*)d_in[7];
    const float* B_w     = (const float*)d_in[8];
    const float* C_w     = (const float*)d_in[9];
    const float* out_w   = (const float*)d_in[10];
    float* out = (float*)d_out;

    auto ga = [](const void* sym) { void* p; cudaGetSymbolAddress(&p, sym); return p; };
    __half* xh  = (__half*)ga(g_xh);
    __half* wzh = (__half*)ga(g_wzh);
    __half* wth = (__half*)ga(g_wth);
    __half* Ph  = (__half*)ga(g_Ph);
    __half* Mbh = (__half*)ga(g_Mbh);
    __half* dwh = (__half*)ga(g_dwh);
    __half* owh = (__half*)ga(g_owh);
    __half* uh  = (__half*)ga(g_uh);
    __half* sh  = (__half*)ga(g_sh);
    float*  dtp = (float*)ga(g_dt);
    __half* yh  = (__half*)ga(g_yh);
    float*  Bm  = (float*)ga(g_Bm);
    float*  Cm  = (float*)ga(g_Cm);

    cudaFuncSetAttribute(tgemm<0,0,false,3>, cudaFuncAttributeMaxDynamicSharedMemorySize, GSMEM);
    cudaFuncSetAttribute(tgemm<0,1,false,1>, cudaFuncAttributeMaxDynamicSharedMemorySize, GSMEM);
    cudaFuncSetAttribute(tgemm<1,0,true,1>,  cudaFuncAttributeMaxDynamicSharedMemorySize, GSMEM);
    cudaFuncSetAttribute(tgemm<0,2,true,0>,  cudaFuncAttributeMaxDynamicSharedMemorySize, GSMEM);
    cudaFuncSetAttribute(tgemm<0,0,false,0>, cudaFuncAttributeMaxDynamicSharedMemorySize, GSMEM);

    // conversions
    convert_batch<<<12288, 256>>>(x, in_proj + (size_t)DINNER * DMODEL, dt_w, out_w);
    tsplit_k<<<dim3(32, 64), 256>>>(in_proj, wth);                       // WxcT
    pack_split_k<<<16384, 256>>>(conv_w);                                // conv taps

    // fold: M_k = P_k @ Wxc (M=8192, N=1024, K=2048) -> writes Mbh directly (remap)
    tgemm<0,0,false,3><<<dim3(8, 64), 256, GSMEM>>>(
        Ph, wth, nullptr, nullptr, Mbh, 8192, 1024, 2048);

    // silu(z) = silu(x @ Wz^T) -> f16 sh
    tgemm<0,1,false,1><<<dim3(16, 32), 256, GSMEM>>>(
        xh, wzh, nullptr, nullptr, sh, NTOK, DINNER, DMODEL);

    // u = conv fold (shifted K=4096) + conv_b -> f16 uh only
    tgemm<1,0,true,1><<<dim3(16, 32), 256, GSMEM>>>(
        xh, Mbh, conv_b, nullptr, uh, NTOK, DINNER, 4 * DMODEL);

    // dt = clip(sigmoid(u @ dt_w^T + dt_b)) -> fp32
    tgemm<0,2,true,0><<<dim3(16, 32), 256, GSMEM>>>(
        uh, dwh, dt_b, dtp, nullptr, NTOK, DINNER, DINNER);

    // B/C projections (read f16 u)
    bc_gemm<<<NTOK / 32, 256>>>(uh, B_w, C_w);

    // selective scan -> yh (f16)
    scan_k<<<128, 512>>>(uh, dtp, Bm, Cm, A_log, Dp, sh, yh);

    // out = y @ out_w^T -> fp32 d_out
    tgemm<0,0,false,0><<<dim3(8, 32), 256, GSMEM>>>(
        yh, owh, nullptr, out, nullptr, NTOK, DMODEL, DINNER);
}

// round 12
// speedup vs baseline: 1.5993x; 1.0442x over previous
#include <cuda_runtime.h>
#include <cuda_fp16.h>
#include <math.h>
#include <stdint.h>

#define DMODEL 1024
#define DINNER 2048
#define DSTATE 16
#define SEQLEN 2048
#define NTOK   4096   /* BATCH * SEQLEN */

// ---------------- scratch (device globals; no runtime allocation) ----------------
__device__ __half g_xh [NTOK * DMODEL];
__device__ __half g_wzh[DINNER * DMODEL];
__device__ __half g_wth[DMODEL * DINNER];     // WxcT hi
__device__ __half g_Ph [4u * DINNER * DINNER];
__device__ __half g_Mbh[DINNER * 4 * DMODEL]; // folded conv weights, conv layout
__device__ __half g_dwh[DINNER * DINNER];
__device__ __half g_owh[DMODEL * DINNER];
__device__ __half g_uh [NTOK * DINNER];       // conv output (f16 only)
__device__ __half g_sh [NTOK * DINNER];       // silu(z) (f16 only)
__device__ float  g_dt [NTOK * DINNER];       // dt kept fp32 (exp-argument sensitivity)
__device__ __half g_yh [NTOK * DINNER];
__device__ float  g_Bm [NTOK * DSTATE], g_Cm [NTOK * DSTATE];

// ---------------- helpers ----------------
__device__ __forceinline__ uint32_t smem_u32(const void* p) {
    uint32_t a;
    asm("{ .reg .u64 t; cvta.to.shared.u64 t, %1; cvt.u32.u64 %0, t; }" : "=r"(a) : "l"(p));
    return a;
}

#define LDSM4(r, a) asm volatile( \
    "ldmatrix.sync.aligned.m8n8.x4.shared.b16 {%0,%1,%2,%3}, [%4];" \
    : "=r"((r)[0]), "=r"((r)[1]), "=r"((r)[2]), "=r"((r)[3]) : "r"(a))

#define MMAF32(c, a, b0, b1) asm volatile( \
    "mma.sync.aligned.m16n8k16.row.col.f32.f16.f16.f32 " \
    "{%0,%1,%2,%3},{%4,%5,%6,%7},{%8,%9},{%0,%1,%2,%3};" \
    : "+f"((c)[0]), "+f"((c)[1]), "+f"((c)[2]), "+f"((c)[3]) \
    : "r"((a)[0]), "r"((a)[1]), "r"((a)[2]), "r"((a)[3]), "r"(b0), "r"(b1))

#define CPA(dst, src, sz) asm volatile( \
    "cp.async.cg.shared.global [%0], [%1], 16, %2;" :: "r"(dst), "l"(src), "r"(sz))

// ---------------- conversion kernels ----------------
// batched hi-only split: x (4096 blk), Wz (2048), dt_w (4096), out_w (2048)
__global__ void convert_batch(const float* __restrict__ x, const float* __restrict__ wz,
                              const float* __restrict__ dtw, const float* __restrict__ ow) {
    int b = blockIdx.x;
    const float* in;
    __half* h;
    int i;
    if (b < 4096)        { in = x;   h = g_xh;  i = b * 256 + threadIdx.x; }
    else if (b < 6144)   { in = wz;  h = g_wzh; i = (b - 4096) * 256 + threadIdx.x; }
    else if (b < 10240)  { in = dtw; h = g_dwh; i = (b - 6144) * 256 + threadIdx.x; }
    else                 { in = ow;  h = g_owh; i = (b - 10240) * 256 + threadIdx.x; }
    float4 v = reinterpret_cast<const float4*>(in)[i];
    reinterpret_cast<__half2*>(h)[2 * i]     = __floats2half2_rn(v.x, v.y);
    reinterpret_cast<__half2*>(h)[2 * i + 1] = __floats2half2_rn(v.z, v.w);
}

// transpose hi: in_proj rows 0..2047 ([2048,1024]) -> WxcT [1024,2048]
__global__ void tsplit_k(const float* __restrict__ w, __half* __restrict__ th) {
    __shared__ float t[32][33];
    int j0 = blockIdx.x * 32, i0 = blockIdx.y * 32;
    int tx = threadIdx.x & 31, ty4 = threadIdx.x >> 5;
#pragma unroll
    for (int s = 0; s < 4; s++) {
        int ty = ty4 + s * 8;
        t[ty][tx] = w[(size_t)(i0 + ty) * DMODEL + j0 + tx];
    }
    __syncthreads();
#pragma unroll
    for (int s = 0; s < 4; s++) {
        int ty = ty4 + s * 8;
        th[(size_t)(j0 + ty) * DINNER + i0 + tx] = __float2half_rn(t[tx][ty]);
    }
}

// conv_w [d][i][4] -> P_hi [tap][d][i]
__global__ void pack_split_k(const float* __restrict__ cw) {
    int g = blockIdx.x * 256 + threadIdx.x;
    float4 v = reinterpret_cast<const float4*>(cw)[g];
    float vv[4] = {v.x, v.y, v.z, v.w};
#pragma unroll
    for (int t = 0; t < 4; t++)
        g_Ph[(size_t)t * 4194304u + g] = __float2half_rn(vv[t]);
}

// ---------------- HMMA 1-pass GEMM: D = A @ B^T (both operands K-major) ----------------
// MODE 0: normal. MODE 1: conv-fold (A = x with per-1024-K-chunk row shift tap-3).
// EPI 0: none, 1: silu, 2: sigmoid+clip. HASB: +bias[n].
// OUT 0: f32 -> out. OUT 1: f16 -> oh. OUT 3: fold remap f16 -> oh (Mb layout).
#define KTILE   64
#define PITCH_B 144                // 64 halves data + 16B pad -> conflict-free ldmatrix
#define MATB    (128 * PITCH_B)    // 18432 B per matrix tile
#define NSTAGE  3
#define GSMEM   (NSTAGE * 2 * MATB)   // 110592 B (Ah, Bh) -> 2 CTAs/SM

template<int MODE, int EPI, bool HASB, int OUT>
__global__ __launch_bounds__(256, 2)
void tgemm(const __half* __restrict__ Ah, const __half* __restrict__ Bh,
           const float* __restrict__ bias, float* __restrict__ out,
           __half* __restrict__ oh,
           int M, int N, int K)
{
    extern __shared__ char sm_[];
    const int tid = threadIdx.x, lane = tid & 31, wid = tid >> 5;
    const int m0 = blockIdx.y * 128, n0 = blockIdx.x * 128;
    const uint32_t sb = smem_u32(sm_);

    const int wm = wid >> 2, wn = wid & 3;          // warp tile: 64(m) x 32(n)
    const int lr = lane & 15, lc8 = (lane >> 4) * 8;
    const uint32_t aoffH = (uint32_t)((wm * 64 + lr) * PITCH_B + lc8 * 2);
    const uint32_t boffH = (uint32_t)(MATB + (wn * 32 + lr) * PITCH_B + lc8 * 2);

    float acc[4][4][4] = {};

    // stage loader: 8 x 16B chunks per thread (Ah + Bh)
    auto ldst = [&](int kt) {
        const uint32_t st = sb + (kt % NSTAGE) * (2 * MATB);
        const int kb = kt * KTILE;
#pragma unroll
        for (int q = 0; q < 8; q++) {
            int cid = q * 256 + tid;
            int mat = cid >> 10, w = cid & 1023;
            int row = w >> 3, c = w & 7;
            uint32_t dst = st + mat * MATB + row * PITCH_B + c * 16;
            const __half* src;
            uint32_t sz = 16;
            if (mat == 0) {
                if (MODE == 1) {
                    int tap = kb >> 10, jb = kb & 1023, rg = m0 + row;
                    if (((rg & (SEQLEN - 1)) + tap - 3) < 0) { sz = 0; src = Ah; }
                    else src = Ah + (size_t)(rg + tap - 3) * DMODEL + jb + c * 8;
                } else {
                    src = Ah + (size_t)(m0 + row) * K + kb + c * 8;
                }
            } else {
                src = Bh + (size_t)(n0 + row) * K + kb + c * 8;
            }
            CPA(dst, src, sz);
        }
        asm volatile("cp.async.commit_group;" ::: "memory");
    };

    auto comp = [&](int s) {
        const uint32_t st = sb + s * (2 * MATB);
#pragma unroll
        for (int kk = 0; kk < KTILE / 16; kk++) {
            const uint32_t ko = kk * 32;            // 16 halves = 32 bytes
            uint32_t ah[4][4], bhf[2][4];
#pragma unroll
            for (int mt = 0; mt < 4; mt++) LDSM4(ah[mt], st + aoffH + mt * 16 * PITCH_B + ko);
#pragma unroll
            for (int np = 0; np < 2; np++) LDSM4(bhf[np], st + boffH + np * 16 * PITCH_B + ko);
#pragma unroll
            for (int mt = 0; mt < 4; mt++)
#pragma unroll
                for (int nt = 0; nt < 4; nt++)
                    MMAF32(acc[mt][nt], ah[mt], bhf[nt >> 1][nt & 1], bhf[nt >> 1][2 + (nt & 1)]);
        }
    };

    const int nk = K / KTILE;
    ldst(0);
    ldst(1);
    for (int kt = 0; kt < nk; kt++) {
        if (kt + 1 < nk) asm volatile("cp.async.wait_group 1;" ::: "memory");
        else             asm volatile("cp.async.wait_group 0;" ::: "memory");
        __syncthreads();
        if (kt + 2 < nk) ldst(kt + 2);
        comp(kt % NSTAGE);
    }

    // epilogue from register accumulators
    const int g = lane >> 2, tg = lane & 3;
#pragma unroll
    for (int mt = 0; mt < 4; mt++) {
#pragma unroll
        for (int nt = 0; nt < 4; nt++) {
            const int col = n0 + wn * 32 + nt * 8 + tg * 2;
            float b0 = 0.f, b1 = 0.f;
            if (HASB) { b0 = bias[col]; b1 = bias[col + 1]; }
#pragma unroll
            for (int h = 0; h < 2; h++) {
                const int r = m0 + wm * 64 + mt * 16 + g + h * 8;
                float v0 = acc[mt][nt][2 * h + 0] + b0;
                float v1 = acc[mt][nt][2 * h + 1] + b1;
                if (EPI == 1) {
                    v0 = v0 / (1.f + __expf(-v0));
                    v1 = v1 / (1.f + __expf(-v1));
                } else if (EPI == 2) {
                    v0 = fminf(fmaxf(1.f / (1.f + __expf(-v0)), 1e-4f), 1.f);
                    v1 = fminf(fmaxf(1.f / (1.f + __expf(-v1)), 1e-4f), 1.f);
                }
                if (OUT == 3) {
                    // fold remap: m = tap*2048 + d  ->  Mb[d][tap*1024 + col], f16 only
                    size_t dst = (size_t)(r & 2047) * 4096 + (size_t)(r >> 11) * 1024 + col;
                    *reinterpret_cast<__half2*>(oh + dst) = __floats2half2_rn(v0, v1);
                } else if (OUT == 1) {
                    *reinterpret_cast<__half2*>(oh + (size_t)r * N + col) = __floats2half2_rn(v0, v1);
                } else {
                    *reinterpret_cast<float2*>(out + (size_t)r * N + col) = make_float2(v0, v1);
                }
            }
        }
    }
}

// ---------------- small B/C projection GEMM (reads f16 u) ----------------
__global__ __launch_bounds__(256)
void bc_gemm(const __half* __restrict__ uh, const float* __restrict__ Bw,
             const float* __restrict__ Cw)
{
    __shared__ float us[32][65];
    __shared__ float ws[32][65];
    const int tid  = threadIdx.x;
    const int row0 = blockIdx.x * 32;
    const int c  = tid & 31;
    const int rq = tid >> 5;
    float acc[4] = {0.f, 0.f, 0.f, 0.f};

    for (int kt = 0; kt < DINNER; kt += 64) {
        __syncthreads();
#pragma unroll
        for (int s = 0; s < 8; s++) {
            int e = tid + s * 256;
            int r = e >> 6, k = e & 63;
            us[r][k] = __half2float(uh[(size_t)(row0 + r) * DINNER + kt + k]);
            ws[r][k] = (r < 16) ? Bw[r * DINNER + kt + k]
                                : Cw[(r - 16) * DINNER + kt + k];
        }
        __syncthreads();
#pragma unroll 8
        for (int k = 0; k < 64; k++) {
            float wv = ws[c][k];
#pragma unroll
            for (int i = 0; i < 4; i++)
                acc[i] = fmaf(us[rq * 4 + i][k], wv, acc[i]);
        }
    }
#pragma unroll
    for (int i = 0; i < 4; i++) {
        int row = row0 + rq * 4 + i;
        if (c < 16) g_Bm[(size_t)row * DSTATE + c]        = acc[i];
        else        g_Cm[(size_t)row * DSTATE + (c - 16)] = acc[i];
    }
}

// ---------------- selective scan (f16 u/sz inputs, emits f16 y) ----------------
__global__ __launch_bounds__(512)
void scan_k(const __half* __restrict__ uh, const float* __restrict__ dt,
            const float* __restrict__ Bm, const float* __restrict__ Cm,
            const float* __restrict__ Alog, const float* __restrict__ Dp,
            const __half* __restrict__ szh, __half* __restrict__ yh)
{
    const int tid = threadIdx.x;
    const int b   = blockIdx.x >> 6;
    const int d0  = (blockIdx.x & 63) * 32;
    const int dl  = tid >> 4;
    const int n   = tid & 15;
    const int d   = d0 + dl;
    const float Areg = -expf(Alog[d * DSTATE + n]);
    const float Dreg = Dp[d];
    const size_t rowbase = (size_t)b * SEQLEN;
    float state = 0.f;

    __shared__ float dt_s[2][32][32];
    __shared__ float u_s [2][32][32];
    __shared__ float sz_s[2][32][32];
    __shared__ float B_s [2][32][16];
    __shared__ float C_s [2][32][16];
    __shared__ float y_s [32][32];

    auto stage = [&](int buf, int l0) {
#pragma unroll
        for (int s = 0; s < 2; s++) {
            int e = tid + s * 512;
            int ll = e >> 5, dd = e & 31;
            size_t g = (rowbase + l0 + ll) * DINNER + d0 + dd;
            dt_s[buf][ll][dd] = dt[g];
            u_s [buf][ll][dd] = __half2float(uh[g]);
            sz_s[buf][ll][dd] = __half2float(szh[g]);
        }
        {
            int ll = tid >> 4, nn = tid & 15;
            size_t g = (rowbase + l0 + ll) * DSTATE + nn;
            B_s[buf][ll][nn] = Bm[g];
            C_s[buf][ll][nn] = Cm[g];
        }
    };

    stage(0, 0);
    __syncthreads();
    int buf = 0;
    for (int t = 0; t < SEQLEN / 32; t++) {
        const int l0 = t * 32;
        if (t + 1 < SEQLEN / 32) stage(buf ^ 1, l0 + 32);
#pragma unroll 4
        for (int ll = 0; ll < 32; ll++) {
            float dtv = dt_s[buf][ll][dl];
            float uv  = u_s [buf][ll][dl];
            float Bn  = B_s [buf][ll][n];
            float Cn  = C_s [buf][ll][n];
            float arg = fminf(fmaxf(dtv * Areg, -5.f), 5.f);
            float dA  = __expf(arg);
            float dB  = dtv * uv * Bn;
            state = fmaf(dA, state, dB + 1e-6f);
            float v = state * Cn;
            v += __shfl_xor_sync(0xffffffffu, v, 8);
            v += __shfl_xor_sync(0xffffffffu, v, 4);
            v += __shfl_xor_sync(0xffffffffu, v, 2);
            v += __shfl_xor_sync(0xffffffffu, v, 1);
            if (n == 0) y_s[ll][dl] = v + Dreg * uv;
        }
        __syncthreads();
#pragma unroll
        for (int s = 0; s < 2; s++) {
            int e = tid + s * 512;
            int ll = e >> 5, dd = e & 31;
            size_t g = (rowbase + l0 + ll) * DINNER + d0 + dd;
            yh[g] = __float2half_rn(y_s[ll][dd] * sz_s[buf][ll][dd]);
        }
        __syncthreads();
        buf ^= 1;
    }
}

// ---------------- launch (fork-join stream graph) ----------------
extern "C" void kernel_launch(void* const* d_in, const int* in_sizes, int n_in,
                              void* d_out, int out_size)
{
    (void)in_sizes; (void)n_in; (void)out_size;
    const float* x       = (const float*)d_in[0];
    const float* in_proj = (const float*)d_in[1];
    const float* conv_w  = (const float*)d_in[2];
    const float* conv_b  = (const float*)d_in[3];
    const float* dt_w    = (const float*)d_in[4];
    const float* dt_b    = (const float*)d_in[5];
    const float* A_log   = (const float*)d_in[6];
    const float* Dp      = (const float*)d_in[7];
    const float* B_w     = (const float*)d_in[8];
    const float* C_w     = (const float*)d_in[9];
    const float* out_w   = (const float*)d_in[10];
    float* out = (float*)d_out;

    auto ga = [](const void* sym) { void* p; cudaGetSymbolAddress(&p, sym); return p; };
    __half* xh  = (__half*)ga(g_xh);
    __half* wzh = (__half*)ga(g_wzh);
    __half* wth = (__half*)ga(g_wth);
    __half* Ph  = (__half*)ga(g_Ph);
    __half* Mbh = (__half*)ga(g_Mbh);
    __half* dwh = (__half*)ga(g_dwh);
    __half* owh = (__half*)ga(g_owh);
    __half* uh  = (__half*)ga(g_uh);
    __half* sh  = (__half*)ga(g_sh);
    float*  dtp = (float*)ga(g_dt);
    __half* yh  = (__half*)ga(g_yh);
    float*  Bm  = (float*)ga(g_Bm);
    float*  Cm  = (float*)ga(g_Cm);

    cudaFuncSetAttribute(tgemm<0,0,false,3>, cudaFuncAttributeMaxDynamicSharedMemorySize, GSMEM);
    cudaFuncSetAttribute(tgemm<0,1,false,1>, cudaFuncAttributeMaxDynamicSharedMemorySize, GSMEM);
    cudaFuncSetAttribute(tgemm<1,0,true,1>,  cudaFuncAttributeMaxDynamicSharedMemorySize, GSMEM);
    cudaFuncSetAttribute(tgemm<0,2,true,0>,  cudaFuncAttributeMaxDynamicSharedMemorySize, GSMEM);
    cudaFuncSetAttribute(tgemm<0,0,false,0>, cudaFuncAttributeMaxDynamicSharedMemorySize, GSMEM);

    // fork-join resources (host-side only; become graph edges under capture)
    cudaStream_t s1, s2;
    cudaStreamCreateWithFlags(&s1, cudaStreamNonBlocking);
    cudaStreamCreateWithFlags(&s2, cudaStreamNonBlocking);
    cudaEvent_t evRoot, evFold, evConv, evBC;
    cudaEventCreateWithFlags(&evRoot, cudaEventDisableTiming);
    cudaEventCreateWithFlags(&evFold, cudaEventDisableTiming);
    cudaEventCreateWithFlags(&evConv, cudaEventDisableTiming);
    cudaEventCreateWithFlags(&evBC,   cudaEventDisableTiming);

    // ---- fork: weight-prep branch on s1, main branch on stream 0 ----
    cudaEventRecord(evRoot, 0);
    cudaStreamWaitEvent(s1, evRoot, 0);

    // s1: WxcT transpose, conv-tap pack, fold GEMM -> Mbh
    tsplit_k<<<dim3(32, 64), 256, 0, s1>>>(in_proj, wth);
    pack_split_k<<<16384, 256, 0, s1>>>(conv_w);
    tgemm<0,0,false,3><<<dim3(8, 64), 256, GSMEM, s1>>>(
        Ph, wth, nullptr, nullptr, Mbh, 8192, 1024, 2048);
    cudaEventRecord(evFold, s1);

    // 0: conversions + z GEMM (overlaps fold branch)
    convert_batch<<<12288, 256>>>(x, in_proj + (size_t)DINNER * DMODEL, dt_w, out_w);
    tgemm<0,1,false,1><<<dim3(16, 32), 256, GSMEM>>>(
        xh, wzh, nullptr, nullptr, sh, NTOK, DINNER, DMODEL);

    // join: conv needs Mbh (s1) + xh (0)
    cudaStreamWaitEvent(0, evFold, 0);
    tgemm<1,0,true,1><<<dim3(16, 32), 256, GSMEM>>>(
        xh, Mbh, conv_b, nullptr, uh, NTOK, DINNER, 4 * DMODEL);

    // ---- fork: bc_gemm on s2 overlaps dt GEMM on 0 (both read uh only) ----
    cudaEventRecord(evConv, 0);
    cudaStreamWaitEvent(s2, evConv, 0);
    bc_gemm<<<NTOK / 32, 256, 0, s2>>>(uh, B_w, C_w);
    cudaEventRecord(evBC, s2);

    tgemm<0,2,true,0><<<dim3(16, 32), 256, GSMEM>>>(
        uh, dwh, dt_b, dtp, nullptr, NTOK, DINNER, DINNER);

    // join: scan needs dtp (0) + Bm/Cm (s2) + sh
    cudaStreamWaitEvent(0, evBC, 0);
    scan_k<<<128, 512>>>(uh, dtp, Bm, Cm, A_log, Dp, sh, yh);

    // out = y @ out_w^T -> fp32 d_out
    tgemm<0,0,false,0><<<dim3(8, 32), 256, GSMEM>>>(
        yh, owh, nullptr, out, nullptr, NTOK, DMODEL, DINNER);

    cudaEventDestroy(evRoot);
    cudaEventDestroy(evFold);
    cudaEventDestroy(evConv);
    cudaEventDestroy(evBC);
    cudaStreamDestroy(s1);
    cudaStreamDestroy(s2);
}